// round 16
// baseline (speedup 1.0000x reference)
#include <cuda_runtime.h>
#include <cuda_fp16.h>
#include <cstdint>

#define NB 8
#define NS 512
#define ND 768
#define NH 256
#define NC 32

// ---------------- scratch (device globals) ----------------
__device__ __align__(16) __half g_seq_hi[NB * NS * ND];
__device__ __align__(16) __half g_seq_lo[NB * NS * ND];
__device__ __align__(16) __half g_Wcat_hi[2 * NH * ND];
__device__ float g_bcat[2 * NH];
__device__ __align__(16) __half g_Hs_hi[NB * NS * NH];
__device__ __align__(16) __half g_Hs_lo[NB * NS * NH];
__device__ __align__(16) __half g_He_hi[NB * NS * NH];
__device__ __align__(16) __half g_He_lo[NB * NS * NH];
__device__ __align__(16) __half g_Ur_hi[NC * NH * NH];
__device__ __align__(16) __half g_M[(size_t)NB * NS * NC * NH];
__device__ float g_Le[NB * NS * NC];
__device__ float g_Wsp[NC * NH];

// ---------------- helpers ----------------
__device__ __forceinline__ uint32_t smem_u32(const void* p) {
    uint32_t a;
    asm("{ .reg .u64 t; cvta.to.shared.u64 t, %1; cvt.u32.u64 %0, t; }" : "=r"(a) : "l"(p));
    return a;
}
__device__ __forceinline__ void cp16(uint32_t s, const void* g) {
    asm volatile("cp.async.cg.shared.global [%0], [%1], 16;" :: "r"(s), "l"(g));
}
#define CP_COMMIT() asm volatile("cp.async.commit_group;" ::: "memory")
#define CP_WAIT2()  asm volatile("cp.async.wait_group 2;" ::: "memory")
#define CP_WAIT1()  asm volatile("cp.async.wait_group 1;" ::: "memory")
#define CP_WAIT0()  asm volatile("cp.async.wait_group 0;" ::: "memory")

__device__ __forceinline__ void ldsm4(uint32_t& r0, uint32_t& r1, uint32_t& r2, uint32_t& r3, uint32_t a) {
    asm volatile("ldmatrix.sync.aligned.m8n8.x4.shared.b16 {%0,%1,%2,%3}, [%4];"
                 : "=r"(r0), "=r"(r1), "=r"(r2), "=r"(r3) : "r"(a));
}
__device__ __forceinline__ void mma16816(float* c, const uint32_t* a, uint32_t b0, uint32_t b1) {
    asm volatile("mma.sync.aligned.m16n8k16.row.col.f32.f16.f16.f32 "
                 "{%0,%1,%2,%3}, {%4,%5,%6,%7}, {%8,%9}, {%0,%1,%2,%3};"
                 : "+f"(c[0]), "+f"(c[1]), "+f"(c[2]), "+f"(c[3])
                 : "r"(a[0]), "r"(a[1]), "r"(a[2]), "r"(a[3]), "r"(b0), "r"(b1));
}
__device__ __forceinline__ uint32_t sw128(uint32_t off) {
    return off ^ ((off >> 3) & 0x70);
}
__device__ __forceinline__ void split2h(float v, __half& h, __half& l) {
    h = __float2half_rn(v);
    l = __float2half_rn(v - __half2float(h));
}

// ---------------- fused prep kernel (grid-sectioned) ----------------
#define BLK_SPLIT  6144
#define BLK_U      8192
#define BLK_WCAT   1536
#define BLK_WSP    32
__global__ void prep_kernel(const float* __restrict__ seq, const float* __restrict__ U,
                            const float* __restrict__ W_w,
                            const float* __restrict__ Ws_w, const float* __restrict__ We_w,
                            const float* __restrict__ Ws_b, const float* __restrict__ We_b) {
    int blk = blockIdx.x;
    int tid = threadIdx.x;
    if (blk < BLK_SPLIT) {
        int i = blk * 256 + tid;
        float2 v = reinterpret_cast<const float2*>(seq)[i];
        __half h0, l0, h1, l1;
        split2h(v.x, h0, l0);
        split2h(v.y, h1, l1);
        __half2 hh; hh.x = h0; hh.y = h1;
        __half2 ll; ll.x = l0; ll.y = l1;
        reinterpret_cast<__half2*>(g_seq_hi)[i] = hh;
        reinterpret_cast<__half2*>(g_seq_lo)[i] = ll;
    } else if (blk < BLK_SPLIT + BLK_U) {
        int idx = (blk - BLK_SPLIT) * 256 + tid;
        int g = idx & 255, h = (idx >> 8) & 255, c = idx >> 16;
        g_Ur_hi[idx] = __float2half_rn(U[(size_t)h * (NC * NH) + c * NH + g]);
    } else if (blk < BLK_SPLIT + BLK_U + BLK_WCAT) {
        int i = (blk - BLK_SPLIT - BLK_U) * 256 + tid;
        int n = i / ND, d = i - n * ND;
        float v = (n < NH) ? Ws_w[n * ND + d] : We_w[(n - NH) * ND + d];
        g_Wcat_hi[i] = __float2half_rn(v);
        if (i < 2 * NH) g_bcat[i] = (i < NH) ? Ws_b[i] : We_b[i - NH];
    } else {
        int i = (blk - BLK_SPLIT - BLK_U - BLK_WCAT) * 256 + tid;
        g_Wsp[i] = W_w[(i >> 8) * 512 + (i & 255)];
    }
}

// Le[row, c] = He[row,:] . W_w[c, 256:512] + W_b[c]
__global__ void __launch_bounds__(256) le_kernel(const float* __restrict__ W_w,
                                                 const float* __restrict__ W_b) {
    __shared__ float We[32][258];
    int tid = threadIdx.x;
    for (int i = tid; i < 32 * 256; i += 256) {
        int c = i >> 8, g = i & 255;
        We[c][g] = W_w[c * 512 + 256 + g];
    }
    __syncthreads();
    int c = tid & 31, r = tid >> 5;
    int row = blockIdx.x * 8 + r;
    const __half2* hh = reinterpret_cast<const __half2*>(g_He_hi + (size_t)row * NH);
    const __half2* hl = reinterpret_cast<const __half2*>(g_He_lo + (size_t)row * NH);
    float acc = 0.f;
#pragma unroll 8
    for (int g = 0; g < 128; ++g) {
        float2 h2 = __half22float2(hh[g]);
        float2 l2 = __half22float2(hl[g]);
        acc = fmaf(h2.x + l2.x, We[c][2 * g], acc);
        acc = fmaf(h2.y + l2.y, We[c][2 * g + 1], acc);
    }
    g_Le[(size_t)row * NC + c] = acc + W_b[c];
}

// ---------------- projection GEMM (proven R14 config: P=2, TN=128, ST=2, 512 thr) ----------------
__global__ void __launch_bounds__(512) gemm_proj(
    const __half* __restrict__ A0, const __half* __restrict__ A1,
    const __half* __restrict__ B0,
    const float* __restrict__ aux,
    __half* __restrict__ Oh, __half* __restrict__ Ol,
    __half* __restrict__ Oh2, __half* __restrict__ Ol2)
{
    constexpr int K = ND;
    constexpr uint32_t TILE_A = 16384;
    constexpr uint32_t TILE_BB = 16384;
    constexpr uint32_t OFF_B0 = TILE_A;
    constexpr uint32_t OFF_A1 = TILE_A + TILE_BB;
    constexpr uint32_t STAGE = 2 * TILE_A + TILE_BB;

    extern __shared__ char smem[];
    const uint32_t sb = smem_u32(smem);

    const int tid  = threadIdx.x;
    const int wid  = tid >> 5;
    const int lane = tid & 31;
    const int bm   = blockIdx.x * 128;
    const int bn   = blockIdx.y * 128;

    const int fr = tid >> 3;
    const int fk = tid & 7;
    const int wm = (wid & 1) * 64;
    const int wn = (wid >> 1) * 16;
    const int lrow = lane & 15;
    const int lhalf = lane >> 4;

    float acc[4][2][4] = {};

    auto fill = [&](int c, int s) {
        const int ko = c * 64;
        const uint32_t base = sb + s * STAGE;
#pragma unroll
        for (int i = 0; i < 2; ++i) {
            int r = fr + i * 64;
            uint32_t d = sw128((uint32_t)(r * 128 + fk * 16));
            cp16(base + d,          A0 + (size_t)(bm + r) * K + ko + fk * 8);
            cp16(base + OFF_A1 + d, A1 + (size_t)(bm + r) * K + ko + fk * 8);
            cp16(base + OFF_B0 + d, B0 + (size_t)(bn + r) * K + ko + fk * 8);
        }
        CP_COMMIT();
    };

    auto compute = [&](int s) {
        const uint32_t a0b = sb + s * STAGE;
        const uint32_t b0b = a0b + OFF_B0;
        const uint32_t a1b = a0b + OFF_A1;
#pragma unroll
        for (int ks = 0; ks < 4; ++ks) {
            const uint32_t coff = (uint32_t)(ks * 32 + lhalf * 16);
            uint32_t a0f[4][4];
#pragma unroll
            for (int mt = 0; mt < 4; ++mt) {
                int row = wm + mt * 16 + lrow;
                ldsm4(a0f[mt][0], a0f[mt][1], a0f[mt][2], a0f[mt][3],
                      a0b + sw128((uint32_t)(row * 128) + coff));
            }
            uint32_t b0f[4];
            {
                int row = wn + lrow;
                ldsm4(b0f[0], b0f[1], b0f[2], b0f[3],
                      b0b + sw128((uint32_t)(row * 128) + coff));
            }
#pragma unroll
            for (int mt = 0; mt < 4; ++mt)
#pragma unroll
                for (int nt = 0; nt < 2; ++nt)
                    mma16816(acc[mt][nt], a0f[mt], b0f[nt], b0f[nt + 2]);
            uint32_t a1f[4][4];
#pragma unroll
            for (int mt = 0; mt < 4; ++mt) {
                int row = wm + mt * 16 + lrow;
                ldsm4(a1f[mt][0], a1f[mt][1], a1f[mt][2], a1f[mt][3],
                      a1b + sw128((uint32_t)(row * 128) + coff));
            }
#pragma unroll
            for (int mt = 0; mt < 4; ++mt)
#pragma unroll
                for (int nt = 0; nt < 2; ++nt)
                    mma16816(acc[mt][nt], a1f[mt], b0f[nt], b0f[nt + 2]);
        }
    };

    const int nchunks = K >> 6;
    fill(0, 0);
    for (int c = 0; c < nchunks; ++c) {
        const int s = c & 1;
        if (c + 1 < nchunks) { fill(c + 1, s ^ 1); CP_WAIT1(); }
        else CP_WAIT0();
        __syncthreads();
        compute(s);
        __syncthreads();
    }

    const int rbase = bm + wm + (lane >> 2);
    const int cb0 = bn + wn + (lane & 3) * 2;
#pragma unroll
    for (int mt = 0; mt < 4; ++mt)
#pragma unroll
        for (int nt = 0; nt < 2; ++nt) {
            int cn = cb0 + nt * 8;
#pragma unroll
            for (int h = 0; h < 2; ++h) {
                int r = rbase + mt * 16 + h * 8;
                float v0 = acc[mt][nt][h * 2 + 0] + aux[cn];
                float v1 = acc[mt][nt][h * 2 + 1] + aux[cn + 1];
                __half h0, l0, h1, l1;
                split2h(v0, h0, l0);
                split2h(v1, h1, l1);
                __half2 th; th.x = h0; th.y = h1;
                __half2 tl; tl.x = l0; tl.y = l1;
                if (cn < NH) {
                    *reinterpret_cast<__half2*>(Oh + (size_t)r * NH + cn) = th;
                    *reinterpret_cast<__half2*>(Ol + (size_t)r * NH + cn) = tl;
                } else {
                    *reinterpret_cast<__half2*>(Oh2 + (size_t)r * NH + cn - NH) = th;
                    *reinterpret_cast<__half2*>(Ol2 + (size_t)r * NH + cn - NH) = tl;
                }
            }
        }
}

// ---------------- persistent streaming GEMM (A resident, B streamed) ----------------
// A: 128 x 256 fp16 resident (64KB).  B n-blocks: 256 x 256, streamed in 4 k-chunks
// of 64 through a 4-stage ring (stage = 32KB), single __syncthreads per chunk,
// no drain between n-blocks.  512 threads, 16 warps (2m x 8n), warp tile 64x32.
// MODE 1: Oh fp16 = acc + aux[n]            (GEMM1: M = He@Ur^T + Wsp)
// MODE 2: Of fp32 = acc + aux[b*NS*NC + n]  (GEMM2: out = Hs@M^T + Le), streaming stores
template<int MODE>
__global__ void __launch_bounds__(512) gemm_stream(
    const __half* __restrict__ A, const __half* __restrict__ B,
    long sA, long sB,
    const float* __restrict__ aux,
    __half* __restrict__ Oh, float* __restrict__ Of,
    int ldc, long sC, int nblk_per)
{
    constexpr uint32_t OFF_B = 65536;

    extern __shared__ char smem[];
    const uint32_t sb = smem_u32(smem);

    const int tid = threadIdx.x;
    const int wid = tid >> 5, lane = tid & 31;
    const int bm  = blockIdx.x * 128;
    const int b   = blockIdx.z;
    const int nb0 = blockIdx.y * nblk_per;

    const __half* Ag = A + (size_t)b * sA;
    const __half* Bg = B + (size_t)b * sB;

    const int wm = (wid & 1) * 64;
    const int wn = (wid >> 1) * 32;
    const int lrow = lane & 15, lhalf = lane >> 4;

    const int total = nblk_per * 4;

    auto fillA = [&] {
#pragma unroll
        for (int i = 0; i < 8; ++i) {
            int u = tid + i * 512;
            int kc = u >> 10, rem = u & 1023, r = rem >> 3, un = rem & 7;
            cp16(sb + kc * 16384 + sw128((uint32_t)(r * 128 + un * 16)),
                 Ag + (size_t)(bm + r) * 256 + kc * 64 + un * 8);
        }
    };
    auto fillB = [&](int t) {
        int nb = nb0 + (t >> 2), kc = t & 3;
        const uint32_t base = sb + OFF_B + (uint32_t)(t & 3) * 32768;
        const __half* Bgr = Bg + (size_t)nb * 65536 + kc * 64;
#pragma unroll
        for (int i = 0; i < 4; ++i) {
            int u = tid + i * 512;
            int r = u >> 3, un = u & 7;
            cp16(base + sw128((uint32_t)(r * 128 + un * 16)),
                 Bgr + (size_t)r * 256 + un * 8);
        }
        CP_COMMIT();
    };

    float acc[4][4][4];

    fillA();
    fillB(0);            // group 0 = {A tile, B chunk 0}
    if (total > 1) fillB(1);

    for (int t = 0; t < total; ++t) {
        if (t + 2 < total) { fillB(t + 2); CP_WAIT2(); }
        else if (t + 1 < total) CP_WAIT1();
        else CP_WAIT0();
        __syncthreads();

        const int kc = t & 3;
        if (kc == 0) {
#pragma unroll
            for (int mt = 0; mt < 4; ++mt)
#pragma unroll
                for (int nt = 0; nt < 4; ++nt)
#pragma unroll
                    for (int j = 0; j < 4; ++j) acc[mt][nt][j] = 0.f;
        }

        const uint32_t a0b = sb + kc * 16384;
        const uint32_t b0b = sb + OFF_B + (uint32_t)kc * 32768;
#pragma unroll
        for (int ks = 0; ks < 4; ++ks) {
            const uint32_t coff = (uint32_t)(ks * 32 + lhalf * 16);
            uint32_t a0f[4][4];
#pragma unroll
            for (int mt = 0; mt < 4; ++mt) {
                int row = wm + mt * 16 + lrow;
                ldsm4(a0f[mt][0], a0f[mt][1], a0f[mt][2], a0f[mt][3],
                      a0b + sw128((uint32_t)(row * 128) + coff));
            }
            uint32_t b0f[2][4];
#pragma unroll
            for (int bp = 0; bp < 2; ++bp) {
                int row = wn + bp * 16 + lrow;
                ldsm4(b0f[bp][0], b0f[bp][1], b0f[bp][2], b0f[bp][3],
                      b0b + sw128((uint32_t)(row * 128) + coff));
            }
#pragma unroll
            for (int mt = 0; mt < 4; ++mt)
#pragma unroll
                for (int nt = 0; nt < 4; ++nt) {
                    int bp = nt >> 1, q = nt & 1;
                    mma16816(acc[mt][nt], a0f[mt], b0f[bp][q], b0f[bp][q + 2]);
                }
        }

        if (kc == 3) {
            // epilogue for this n-block (register->global; no smem, no barrier)
            const int nbg = (nb0 + (t >> 2)) * 256;
            const int rbase = bm + wm + (lane >> 2);
            const int cb0 = wn + (lane & 3) * 2;
#pragma unroll
            for (int mt = 0; mt < 4; ++mt)
#pragma unroll
                for (int nt = 0; nt < 4; ++nt) {
                    int cn = nbg + cb0 + nt * 8;
#pragma unroll
                    for (int h = 0; h < 2; ++h) {
                        int r = rbase + mt * 16 + h * 8;
                        float v0 = acc[mt][nt][h * 2 + 0];
                        float v1 = acc[mt][nt][h * 2 + 1];
                        if (MODE == 1) {
                            v0 += aux[cn]; v1 += aux[cn + 1];
                            __half2 o; o.x = __float2half_rn(v0); o.y = __float2half_rn(v1);
                            *reinterpret_cast<__half2*>(Oh + (size_t)b * sC + (size_t)r * ldc + cn) = o;
                        } else {
                            const float* le = aux + (size_t)b * (NS * NC);
                            float2 o;
                            o.x = v0 + le[cn];
                            o.y = v1 + le[cn + 1];
                            __stcs(reinterpret_cast<float2*>(Of + (size_t)b * sC + (size_t)r * ldc + cn), o);
                        }
                    }
                }
        }
    }
}

// ---------------- launch ----------------
extern "C" void kernel_launch(void* const* d_in, const int* in_sizes, int n_in,
                              void* d_out, int out_size) {
    const float* seq  = (const float*)d_in[0];
    const float* U    = (const float*)d_in[1];
    const float* W_w  = (const float*)d_in[2];
    const float* W_b  = (const float*)d_in[3];
    const float* Ws_w = (const float*)d_in[4];
    const float* Ws_b = (const float*)d_in[5];
    const float* We_w = (const float*)d_in[6];
    const float* We_b = (const float*)d_in[7];
    float* out = (float*)d_out;

    __half *seq_hi, *seq_lo, *Wc_hi, *Hs_hi, *Hs_lo, *He_hi, *He_lo, *Ur_hi, *M;
    float *bcat, *Le, *Wsp;
    cudaGetSymbolAddress((void**)&seq_hi, g_seq_hi);
    cudaGetSymbolAddress((void**)&seq_lo, g_seq_lo);
    cudaGetSymbolAddress((void**)&Wc_hi,  g_Wcat_hi);
    cudaGetSymbolAddress((void**)&bcat,   g_bcat);
    cudaGetSymbolAddress((void**)&Hs_hi,  g_Hs_hi);
    cudaGetSymbolAddress((void**)&Hs_lo,  g_Hs_lo);
    cudaGetSymbolAddress((void**)&He_hi,  g_He_hi);
    cudaGetSymbolAddress((void**)&He_lo,  g_He_lo);
    cudaGetSymbolAddress((void**)&Ur_hi,  g_Ur_hi);
    cudaGetSymbolAddress((void**)&M,      g_M);
    cudaGetSymbolAddress((void**)&Le,     g_Le);
    cudaGetSymbolAddress((void**)&Wsp,    g_Wsp);

    const int SMEM_PROJ = 2 * 3 * 16384;            // 96 KB
    const int SMEM_STRM = 65536 + 4 * 32768;        // 192 KB
    cudaFuncSetAttribute(gemm_proj, cudaFuncAttributeMaxDynamicSharedMemorySize, SMEM_PROJ);
    cudaFuncSetAttribute(gemm_stream<1>, cudaFuncAttributeMaxDynamicSharedMemorySize, SMEM_STRM);
    cudaFuncSetAttribute(gemm_stream<2>, cudaFuncAttributeMaxDynamicSharedMemorySize, SMEM_STRM);

    // fused prep
    prep_kernel<<<BLK_SPLIT + BLK_U + BLK_WCAT + BLK_WSP, 256>>>(
        seq, U, W_w, Ws_w, We_w, Ws_b, We_b);

    // fused projections: [Hs | He] = (seq_hi+seq_lo) @ Wcat_hi^T + bcat  (4096 x 512 x 768)
    gemm_proj<<<dim3(32, 4, 1), 512, SMEM_PROJ>>>(
        seq_hi, seq_lo, Wc_hi, bcat, Hs_hi, Hs_lo, He_hi, He_lo);

    le_kernel<<<(NB * NS) / 8, 256>>>(W_w, W_b);

    // GEMM1: M[b, e, (c,h)] = He_hi_b @ Ur_hi^T + Wsp  (512 x 8192 x 256), 8 n-blocks/CTA
    gemm_stream<1><<<dim3(4, 4, NB), 512, SMEM_STRM>>>(
        He_hi, Ur_hi, (long)NS * NH, 0L,
        Wsp, M, nullptr, NC * NH, (long)NS * NC * NH, 8);

    // GEMM2: out[b, s, (e,c)] = Hs_hi_b @ M_b^T + Le   (512 x 16384 x 256), 16 n-blocks/CTA
    gemm_stream<2><<<dim3(4, 4, NB), 512, SMEM_STRM>>>(
        Hs_hi, M, (long)NS * NH, (long)NS * NC * NH,
        Le, nullptr, out, NS * NC, (long)NS * NS * NC, 16);
}

// round 17
// speedup vs baseline: 1.0207x; 1.0207x over previous
#include <cuda_runtime.h>
#include <cuda_fp16.h>
#include <cstdint>

#define NB 8
#define NS 512
#define ND 768
#define NH 256
#define NC 32

// ---------------- scratch (device globals) ----------------
__device__ __align__(16) __half g_seq_hi[NB * NS * ND];
__device__ __align__(16) __half g_seq_lo[NB * NS * ND];
__device__ __align__(16) __half g_Wcat_hi[2 * NH * ND];   // rows 0-255 Ws_w, 256-511 We_w
__device__ float g_bcat[2 * NH];
__device__ __align__(16) __half g_Hs_hi[NB * NS * NH];
__device__ __align__(16) __half g_He_hi[NB * NS * NH];
__device__ __align__(16) __half g_He_lo[NB * NS * NH];
__device__ __align__(16) __half g_Ur_hi[NC * NH * NH];
__device__ __align__(16) __half g_M[(size_t)NB * NS * NC * NH];   // single fp16
__device__ float g_Le[NB * NS * NC];
__device__ float g_Wsp[NC * NH];

// ---------------- helpers ----------------
__device__ __forceinline__ uint32_t smem_u32(const void* p) {
    uint32_t a;
    asm("{ .reg .u64 t; cvta.to.shared.u64 t, %1; cvt.u32.u64 %0, t; }" : "=r"(a) : "l"(p));
    return a;
}
__device__ __forceinline__ void cp16(uint32_t s, const void* g) {
    asm volatile("cp.async.cg.shared.global [%0], [%1], 16;" :: "r"(s), "l"(g));
}
#define CP_COMMIT() asm volatile("cp.async.commit_group;" ::: "memory")
#define CP_WAIT2()  asm volatile("cp.async.wait_group 2;" ::: "memory")
#define CP_WAIT1()  asm volatile("cp.async.wait_group 1;" ::: "memory")
#define CP_WAIT0()  asm volatile("cp.async.wait_group 0;" ::: "memory")

__device__ __forceinline__ void ldsm4(uint32_t& r0, uint32_t& r1, uint32_t& r2, uint32_t& r3, uint32_t a) {
    asm volatile("ldmatrix.sync.aligned.m8n8.x4.shared.b16 {%0,%1,%2,%3}, [%4];"
                 : "=r"(r0), "=r"(r1), "=r"(r2), "=r"(r3) : "r"(a));
}
__device__ __forceinline__ void mma16816(float* c, const uint32_t* a, uint32_t b0, uint32_t b1) {
    asm volatile("mma.sync.aligned.m16n8k16.row.col.f32.f16.f16.f32 "
                 "{%0,%1,%2,%3}, {%4,%5,%6,%7}, {%8,%9}, {%0,%1,%2,%3};"
                 : "+f"(c[0]), "+f"(c[1]), "+f"(c[2]), "+f"(c[3])
                 : "r"(a[0]), "r"(a[1]), "r"(a[2]), "r"(a[3]), "r"(b0), "r"(b1));
}
__device__ __forceinline__ uint32_t sw128(uint32_t off) {
    return off ^ ((off >> 3) & 0x70);
}
__device__ __forceinline__ void split2h(float v, __half& h, __half& l) {
    h = __float2half_rn(v);
    l = __float2half_rn(v - __half2float(h));
}
__device__ __forceinline__ void pdl_sync() {
#if defined(__CUDA_ARCH__) && (__CUDA_ARCH__ >= 900)
    cudaGridDependencySynchronize();
#endif
}
__device__ __forceinline__ void pdl_trigger() {
#if defined(__CUDA_ARCH__) && (__CUDA_ARCH__ >= 900)
    cudaTriggerProgrammaticLaunchCompletion();
#endif
}

// ---------------- fused prep kernel (grid-sectioned) ----------------
#define BLK_SPLIT  6144
#define BLK_U      8192
#define BLK_WCAT   1536
#define BLK_WSP    32
__global__ void prep_kernel(const float* __restrict__ seq, const float* __restrict__ U,
                            const float* __restrict__ W_w,
                            const float* __restrict__ Ws_w, const float* __restrict__ We_w,
                            const float* __restrict__ Ws_b, const float* __restrict__ We_b) {
    int blk = blockIdx.x;
    int tid = threadIdx.x;
    if (blk < BLK_SPLIT) {
        int i = blk * 256 + tid;
        float2 v = reinterpret_cast<const float2*>(seq)[i];
        __half h0, l0, h1, l1;
        split2h(v.x, h0, l0);
        split2h(v.y, h1, l1);
        __half2 hh; hh.x = h0; hh.y = h1;
        __half2 ll; ll.x = l0; ll.y = l1;
        reinterpret_cast<__half2*>(g_seq_hi)[i] = hh;
        reinterpret_cast<__half2*>(g_seq_lo)[i] = ll;
    } else if (blk < BLK_SPLIT + BLK_U) {
        int idx = (blk - BLK_SPLIT) * 256 + tid;
        int g = idx & 255, h = (idx >> 8) & 255, c = idx >> 16;
        g_Ur_hi[idx] = __float2half_rn(U[(size_t)h * (NC * NH) + c * NH + g]);
    } else if (blk < BLK_SPLIT + BLK_U + BLK_WCAT) {
        int i = (blk - BLK_SPLIT - BLK_U) * 256 + tid;
        int n = i / ND, d = i - n * ND;
        float v = (n < NH) ? Ws_w[n * ND + d] : We_w[(n - NH) * ND + d];
        g_Wcat_hi[i] = __float2half_rn(v);
        if (i < 2 * NH) g_bcat[i] = (i < NH) ? Ws_b[i] : We_b[i - NH];
    } else {
        int i = (blk - BLK_SPLIT - BLK_U - BLK_WCAT) * 256 + tid;
        g_Wsp[i] = W_w[(i >> 8) * 512 + (i & 255)];
    }
}

// Le[row, c] = He[row,:] . W_w[c, 256:512] + W_b[c]   (He from fp16 hi/lo)
// Triggers PDL completion EARLY: its output (g_Le) is not read by GEMM1, so
// GEMM1 may fully overlap this kernel.
__global__ void __launch_bounds__(256) le_kernel(const float* __restrict__ W_w,
                                                 const float* __restrict__ W_b) {
    pdl_sync();
    pdl_trigger();
    __shared__ float We[32][258];
    int tid = threadIdx.x;
    for (int i = tid; i < 32 * 256; i += 256) {
        int c = i >> 8, g = i & 255;
        We[c][g] = W_w[c * 512 + 256 + g];
    }
    __syncthreads();
    int c = tid & 31, r = tid >> 5;
    int row = blockIdx.x * 8 + r;
    const __half2* hh = reinterpret_cast<const __half2*>(g_He_hi + (size_t)row * NH);
    const __half2* hl = reinterpret_cast<const __half2*>(g_He_lo + (size_t)row * NH);
    float acc = 0.f;
#pragma unroll 8
    for (int g = 0; g < 128; ++g) {
        float2 h2 = __half22float2(hh[g]);
        float2 l2 = __half22float2(hl[g]);
        acc = fmaf(h2.x + l2.x, We[c][2 * g], acc);
        acc = fmaf(h2.y + l2.y, We[c][2 * g + 1], acc);
    }
    g_Le[(size_t)row * NC + c] = acc + W_b[c];
}

// ---------------- unified HMMA split-fp16 NT GEMM (R13 best config) ----------------
// P=2: (A0,B0)+(A1,B0).  P=1: (A0,B0).
// Tile 128xTN, BK=64, 256 threads, 8 warps (2m x 4n), warp tile 64x(TN/4), ST stages.
// Grid: blockIdx.x = M block (fastest -> B-tile L2 reuse), blockIdx.y = N block.
// MODE 0: proj  -> n<256: store hi only to Oh (Hs); n>=256: hi/lo to (Oh2,Ol2) (He); +bcat[n]
// MODE 1: G1    -> single fp16 Oh, + aux[n]
// MODE 2: G2    -> fp32 Of (streaming stores), + aux[b*NS*NC + n]
template<int P, int MODE, int TN, int ST>
__global__ void __launch_bounds__(256) gemm_mma(
    const __half* __restrict__ A0, const __half* __restrict__ A1,
    const __half* __restrict__ B0,
    long sA, long sB, int K,
    const float* __restrict__ aux,
    __half* __restrict__ Oh,
    __half* __restrict__ Oh2, __half* __restrict__ Ol2,
    float* __restrict__ Of, int ldc, long sC)
{
    pdl_sync();
    constexpr uint32_t TILE_A = 16384;           // 128 rows x 128B
    constexpr uint32_t TILE_BB = TN * 128;       // TN rows x 128B
    constexpr uint32_t OFF_B0 = TILE_A;
    constexpr uint32_t OFF_A1 = TILE_A + TILE_BB;
    constexpr uint32_t STAGE = (P == 2) ? (2 * TILE_A + TILE_BB) : (TILE_A + TILE_BB);
    constexpr int NBP = TN / 64;                 // B ldsm4 loads per ks per warp
    constexpr int NNT = TN / 32;                 // n-subtiles (8 cols each) per warp

    extern __shared__ char smem[];
    const uint32_t sb = smem_u32(smem);

    const int tid  = threadIdx.x;
    const int wid  = tid >> 5;
    const int lane = tid & 31;
    const int b    = blockIdx.z;
    const int bm   = blockIdx.x * 128;
    const int bn   = blockIdx.y * TN;

    const __half* A0g = A0 + (size_t)b * sA;
    const __half* A1g = (P == 2) ? A1 + (size_t)b * sA : nullptr;
    const __half* B0g = B0 + (size_t)b * sB;

    const int fr = tid >> 3;            // 0..31
    const int fk = tid & 7;             // 16B unit in 128B row

    const int wm = (wid & 1) * 64;
    const int wn = (wid >> 1) * (TN / 4);
    const int lrow = lane & 15;
    const int lhalf = lane >> 4;

    float acc[4][NNT][4] = {};

    auto fill = [&](int c, int s) {
        const int ko = c * 64;
        const uint32_t base = sb + s * STAGE;
#pragma unroll
        for (int i = 0; i < 4; ++i) {
            int r = fr + i * 32;
            uint32_t d = sw128((uint32_t)(r * 128 + fk * 16));
            cp16(base + d, A0g + (size_t)(bm + r) * K + ko + fk * 8);
            if (P == 2)
                cp16(base + OFF_A1 + d, A1g + (size_t)(bm + r) * K + ko + fk * 8);
        }
#pragma unroll
        for (int i = 0; i < TN / 32; ++i) {
            int r = fr + i * 32;
            uint32_t d = sw128((uint32_t)(r * 128 + fk * 16));
            cp16(base + OFF_B0 + d, B0g + (size_t)(bn + r) * K + ko + fk * 8);
        }
        CP_COMMIT();
    };

    auto compute = [&](int s) {
        const uint32_t a0b = sb + s * STAGE;
        const uint32_t b0b = a0b + OFF_B0;
        const uint32_t a1b = a0b + OFF_A1;
#pragma unroll
        for (int ks = 0; ks < 4; ++ks) {
            const uint32_t coff = (uint32_t)(ks * 32 + lhalf * 16);
            uint32_t a0f[4][4];
#pragma unroll
            for (int mt = 0; mt < 4; ++mt) {
                int row = wm + mt * 16 + lrow;
                ldsm4(a0f[mt][0], a0f[mt][1], a0f[mt][2], a0f[mt][3],
                      a0b + sw128((uint32_t)(row * 128) + coff));
            }
            uint32_t b0f[NBP][4];
#pragma unroll
            for (int bp = 0; bp < NBP; ++bp) {
                int row = wn + bp * 16 + lrow;
                ldsm4(b0f[bp][0], b0f[bp][1], b0f[bp][2], b0f[bp][3],
                      b0b + sw128((uint32_t)(row * 128) + coff));
            }
#pragma unroll
            for (int mt = 0; mt < 4; ++mt)
#pragma unroll
                for (int nt = 0; nt < NNT; ++nt) {
                    int bp = nt >> 1, q = nt & 1;
                    mma16816(acc[mt][nt], a0f[mt], b0f[bp][q], b0f[bp][q + 2]);
                }
            if (P == 2) {
                uint32_t a1f[4][4];
#pragma unroll
                for (int mt = 0; mt < 4; ++mt) {
                    int row = wm + mt * 16 + lrow;
                    ldsm4(a1f[mt][0], a1f[mt][1], a1f[mt][2], a1f[mt][3],
                          a1b + sw128((uint32_t)(row * 128) + coff));
                }
#pragma unroll
                for (int mt = 0; mt < 4; ++mt)
#pragma unroll
                    for (int nt = 0; nt < NNT; ++nt) {
                        int bp = nt >> 1, q = nt & 1;
                        mma16816(acc[mt][nt], a1f[mt], b0f[bp][q], b0f[bp][q + 2]);
                    }
            }
        }
    };

    const int nchunks = K >> 6;
    fill(0, 0);
    if (ST == 3 && nchunks > 1) fill(1, 1);
    for (int c = 0; c < nchunks; ++c) {
        const int s = c % ST;
        const int nf = c + ST - 1;
        if (nf < nchunks) {
            fill(nf, nf % ST);
            if (ST == 3) CP_WAIT2(); else CP_WAIT1();
        } else if (c + 1 < nchunks) {
            CP_WAIT1();
        } else {
            CP_WAIT0();
        }
        __syncthreads();
        compute(s);
        __syncthreads();
    }

    // ---------------- epilogue ----------------
    const int rbase = bm + wm + (lane >> 2);
    const int cb0 = bn + wn + (lane & 3) * 2;
#pragma unroll
    for (int mt = 0; mt < 4; ++mt)
#pragma unroll
        for (int nt = 0; nt < NNT; ++nt) {
            int r0 = rbase + mt * 16;
            int cn = cb0 + nt * 8;
#pragma unroll
            for (int h = 0; h < 2; ++h) {
                int r = r0 + h * 8;
                float v0 = acc[mt][nt][h * 2 + 0];
                float v1 = acc[mt][nt][h * 2 + 1];
                if (MODE == 0) {
                    v0 += aux[cn]; v1 += aux[cn + 1];
                    if (cn < NH) {
                        // Hs: hi only (lo half unused downstream)
                        __half2 th; th.x = __float2half_rn(v0); th.y = __float2half_rn(v1);
                        *reinterpret_cast<__half2*>(Oh + (size_t)r * NH + cn) = th;
                    } else {
                        __half h0, l0, h1, l1;
                        split2h(v0, h0, l0);
                        split2h(v1, h1, l1);
                        __half2 th; th.x = h0; th.y = h1;
                        __half2 tl; tl.x = l0; tl.y = l1;
                        *reinterpret_cast<__half2*>(Oh2 + (size_t)r * NH + cn - NH) = th;
                        *reinterpret_cast<__half2*>(Ol2 + (size_t)r * NH + cn - NH) = tl;
                    }
                } else if (MODE == 1) {
                    v0 += aux[cn]; v1 += aux[cn + 1];
                    __half2 t; t.x = __float2half_rn(v0); t.y = __float2half_rn(v1);
                    *reinterpret_cast<__half2*>(Oh + (size_t)b * sC + (size_t)r * ldc + cn) = t;
                } else {
                    const float* le = aux + (size_t)b * (NS * NC);
                    float2 t;
                    t.x = v0 + le[cn];
                    t.y = v1 + le[cn + 1];
                    __stcs(reinterpret_cast<float2*>(Of + (size_t)b * sC + (size_t)r * ldc + cn), t);
                }
            }
        }
}

// ---------------- launch ----------------
template<typename F, typename... Args>
static void launch_pdl(F func, dim3 grid, dim3 block, int smem, Args... args) {
    cudaLaunchConfig_t cfg = {};
    cfg.gridDim = grid;
    cfg.blockDim = block;
    cfg.dynamicSmemBytes = (size_t)smem;
    cfg.stream = 0;
    cudaLaunchAttribute attr[1];
    attr[0].id = cudaLaunchAttributeProgrammaticStreamSerialization;
    attr[0].val.programmaticStreamSerializationAllowed = 1;
    cfg.attrs = attr;
    cfg.numAttrs = 1;
    cudaLaunchKernelEx(&cfg, func, args...);
}

extern "C" void kernel_launch(void* const* d_in, const int* in_sizes, int n_in,
                              void* d_out, int out_size) {
    const float* seq  = (const float*)d_in[0];
    const float* U    = (const float*)d_in[1];
    const float* W_w  = (const float*)d_in[2];
    const float* W_b  = (const float*)d_in[3];
    const float* Ws_w = (const float*)d_in[4];
    const float* Ws_b = (const float*)d_in[5];
    const float* We_w = (const float*)d_in[6];
    const float* We_b = (const float*)d_in[7];
    float* out = (float*)d_out;

    __half *seq_hi, *seq_lo, *Wc_hi, *Hs_hi, *He_hi, *He_lo, *Ur_hi, *M;
    float *bcat, *Le, *Wsp;
    cudaGetSymbolAddress((void**)&seq_hi, g_seq_hi);
    cudaGetSymbolAddress((void**)&seq_lo, g_seq_lo);
    cudaGetSymbolAddress((void**)&Wc_hi,  g_Wcat_hi);
    cudaGetSymbolAddress((void**)&bcat,   g_bcat);
    cudaGetSymbolAddress((void**)&Hs_hi,  g_Hs_hi);
    cudaGetSymbolAddress((void**)&He_hi,  g_He_hi);
    cudaGetSymbolAddress((void**)&He_lo,  g_He_lo);
    cudaGetSymbolAddress((void**)&Ur_hi,  g_Ur_hi);
    cudaGetSymbolAddress((void**)&M,      g_M);
    cudaGetSymbolAddress((void**)&Le,     g_Le);
    cudaGetSymbolAddress((void**)&Wsp,    g_Wsp);

    const int SMEM_PROJ = 2 * (2 * 16384 + 16384);          // P=2, TN=128, ST=2: 96 KB
    const int SMEM_BIG  = 3 * (16384 + 256 * 128);          // P=1, TN=256, ST=3: 144 KB
    cudaFuncSetAttribute(gemm_mma<2, 0, 128, 2>, cudaFuncAttributeMaxDynamicSharedMemorySize, SMEM_PROJ);
    cudaFuncSetAttribute(gemm_mma<1, 1, 256, 3>, cudaFuncAttributeMaxDynamicSharedMemorySize, SMEM_BIG);
    cudaFuncSetAttribute(gemm_mma<1, 2, 256, 3>, cudaFuncAttributeMaxDynamicSharedMemorySize, SMEM_BIG);

    // fused prep (plain launch)
    prep_kernel<<<BLK_SPLIT + BLK_U + BLK_WCAT + BLK_WSP, 256>>>(
        seq, U, W_w, Ws_w, We_w, Ws_b, We_b);

    // fused projections: [Hs | He] = (seq_hi+seq_lo) @ Wcat_hi^T + bcat  (4096 x 512 x 768)
    launch_pdl(gemm_mma<2, 0, 128, 2>, dim3(32, 4, 1), dim3(256), SMEM_PROJ,
               (const __half*)seq_hi, (const __half*)seq_lo, (const __half*)Wc_hi,
               0L, 0L, (int)ND,
               (const float*)bcat, Hs_hi, He_hi, He_lo,
               (float*)nullptr, (int)NH, 0L);

    // Le (overlapped by GEMM1 via early PDL trigger)
    launch_pdl(le_kernel, dim3((NB * NS) / 8), dim3(256), 0,
               (const float*)W_w, (const float*)W_b);

    // GEMM1: M[b, e, (c,h)] = He_hi_b @ Ur_hi^T + Wsp -> fp16  (512 x 8192 x 256)
    launch_pdl(gemm_mma<1, 1, 256, 3>, dim3(4, 32, NB), dim3(256), SMEM_BIG,
               (const __half*)He_hi, (const __half*)nullptr, (const __half*)Ur_hi,
               (long)NS * NH, 0L, (int)NH,
               (const float*)Wsp, M, (__half*)nullptr, (__half*)nullptr,
               (float*)nullptr, (int)(NC * NH), (long)NS * NC * NH);

    // GEMM2: out[b, s, (e,c)] = Hs_hi_b @ M_b^T + Le -> fp32   (512 x 16384 x 256)
    launch_pdl(gemm_mma<1, 2, 256, 3>, dim3(4, 64, NB), dim3(256), SMEM_BIG,
               (const __half*)Hs_hi, (const __half*)nullptr, (const __half*)M,
               (long)NS * NH, (long)NS * NC * NH, (int)NH,
               (const float*)Le, (__half*)nullptr, (__half*)nullptr, (__half*)nullptr,
               out, (int)(NS * NC), (long)NS * NS * NC);
}